// round 15
// baseline (speedup 1.0000x reference)
#include <cuda_runtime.h>
#include <cuda_bf16.h>
#include <math.h>
#include <stdint.h>

#define BATCH  32768
#define EMB    256
#define ADIM   64
#define NHEADS 2
#define KNEI   16

// ---------------- scratch (device globals; no allocation allowed) ----------------
__device__ __nv_bfloat16 g_ch [BATCH * EMB];     // center gathered, bf16 hi
__device__ __nv_bfloat16 g_cl [BATCH * EMB];     // center gathered, bf16 lo
__device__ float         g_qk [BATCH * 512];     // qk fp32 (compacted)
__device__ __nv_bfloat16 g_cxh[BATCH * 512];     // ctx hi
__device__ __nv_bfloat16 g_cxl[BATCH * 512];     // ctx lo
__device__ __nv_bfloat16 g_wqh[128 * 256], g_wql[128 * 256];
__device__ __nv_bfloat16 g_wkh[NHEADS * 256 * 64], g_wkl[NHEADS * 256 * 64];  // WkT [h][d][a]
__device__ __nv_bfloat16 g_woh[256 * 512], g_wol[256 * 512];
__device__ int g_valid[BATCH];
__device__ int g_perm [BATCH];    // [0,nv): valid rows, [nv,BATCH): invalid rows
__device__ int g_nvalid;

// ---------------- helpers ----------------
__device__ __forceinline__ uint32_t smem_u32(const void* p) {
    uint32_t a;
    asm("{ .reg .u64 t; cvta.to.shared.u64 t, %1; cvt.u32.u64 %0, t; }" : "=r"(a) : "l"(p));
    return a;
}

#define LDSM4(r0, r1, r2, r3, addr) \
    asm volatile("ldmatrix.sync.aligned.m8n8.x4.shared.b16 {%0,%1,%2,%3}, [%4];" \
                 : "=r"(r0), "=r"(r1), "=r"(r2), "=r"(r3) : "r"(addr))

#define MMA16816(d, a, b0, b1) \
    asm volatile("mma.sync.aligned.m16n8k16.row.col.f32.bf16.bf16.f32 " \
                 "{%0,%1,%2,%3}, {%4,%5,%6,%7}, {%8,%9}, {%0,%1,%2,%3};" \
                 : "+f"((d)[0]), "+f"((d)[1]), "+f"((d)[2]), "+f"((d)[3]) \
                 : "r"((a)[0]), "r"((a)[1]), "r"((a)[2]), "r"((a)[3]), \
                   "r"(b0), "r"(b1))

#define CP16(dst, src) \
    asm volatile("cp.async.cg.shared.global [%0], [%1], 16;" :: "r"(dst), "l"(src) : "memory")
#define CPCOMMIT() asm volatile("cp.async.commit_group;" ::: "memory")
#define CPWAIT1()  asm volatile("cp.async.wait_group 1;" ::: "memory")
#define CPWAIT0()  asm volatile("cp.async.wait_group 0;" ::: "memory")

__device__ __forceinline__ void split1(float v, __nv_bfloat16* hi, __nv_bfloat16* lo) {
    __nv_bfloat16 h = __float2bfloat16(v);
    *hi = h;
    *lo = __float2bfloat16(v - __bfloat162float(h));
}

// ---------------- mask detect + expand + ordered two-sided compaction ----------------
__global__ void mask_compact(const void* __restrict__ mptr) {
    __shared__ int s[1024];
    __shared__ int flag;
    const int t = threadIdx.x;

    if (t == 0) flag = 0;
    __syncthreads();
    const unsigned int* mw = (const unsigned int*)mptr;
    int found = 0;
    for (int i = t; i < 2048; i += 1024)
        if (mw[i] > 1u) found = 1;
    if (found) flag = 1;
    __syncthreads();
    const int byteMode = flag;

    const int base = t * 32;
    int v[32];
    int c = 0;
    #pragma unroll
    for (int i = 0; i < 32; i++) {
        int b = base + i;
        int val = byteMode ? (((const unsigned char*)mptr)[b] != 0)
                           : (((const int*)mptr)[b] != 0);
        v[i] = val;
        g_valid[b] = val;
        c += val;
    }
    s[t] = c;
    __syncthreads();
    for (int off = 1; off < 1024; off <<= 1) {
        int x = (t >= off) ? s[t - off] : 0;
        __syncthreads();
        s[t] += x;
        __syncthreads();
    }
    const int total = s[1023];
    int o  = s[t] - c;
    int oi = total + (base - o);
    #pragma unroll
    for (int i = 0; i < 32; i++) {
        int b = base + i;
        if (v[i]) g_perm[o++]  = b;
        else      g_perm[oi++] = b;
    }
    if (t == 0) g_nvalid = total;
}

// ---------------- merged prep: weight split/transpose + center gather-split ----------------
#define PREP_W 196608
#define PREP_TOT (PREP_W + BATCH * EMB)

__global__ void prep_gather(const float* __restrict__ Wq,
                            const float* __restrict__ Wk,
                            const float* __restrict__ Wout,
                            const float* __restrict__ center) {
    int idx = blockIdx.x * blockDim.x + threadIdx.x;
    if (idx < 32768) {
        split1(Wq[idx], g_wqh + idx, g_wql + idx);
    } else if (idx < 65536) {
        int j = idx - 32768;
        int h = j / (ADIM * EMB);
        int r = j - h * (ADIM * EMB);
        int a = r / EMB;
        int d = r - a * EMB;
        int o = h * EMB * ADIM + d * ADIM + a;
        split1(Wk[j], g_wkh + o, g_wkl + o);
    } else if (idx < PREP_W) {
        int j = idx - 65536;
        split1(Wout[j], g_woh + j, g_wol + j);
    } else {
        int j = idx - PREP_W;
        int row = j >> 8, d = j & 255;
        if (row < g_nvalid) {
            float v = center[(size_t)g_perm[row] * EMB + d];
            split1(v, g_ch + j, g_cl + j);
        }
    }
}

// ======================= q_qk fused kernel constants (BM=64, BN=128) =======================
#define PADB   80
#define MATB_A (64 * PADB)
#define MATB_B (128 * PADB)
#define STGB   (2 * MATB_A + 2 * MATB_B)

#define QSTRIDE 272
#define SQ_HI   0
#define SQ_LO   (64 * QSTRIDE)
#define SB_OFF  (2 * 64 * QSTRIDE)
#define SB_STR  144
#define SB_MATB (128 * SB_STR)
#define FUSED_SMEM (SB_OFF + 2 * SB_MATB)  // 71680

// ======================= out-GEMM constants (BM=128, BN=128) =======================
#define OG_MATB (128 * PADB)
#define OG_STGB (4 * OG_MATB)
#define OG_SMEM (2 * OG_STGB)              // 81920

// ---------------- fused q -> qk kernel (BM=64) ----------------
__global__ __launch_bounds__(256, 2) void q_qk_fused()
{
    extern __shared__ __align__(16) char dynsm[];

    const int nvalid = g_nvalid;
    const int m0 = blockIdx.x * 64;
    if (m0 >= nvalid) return;

    const int t    = threadIdx.x;
    const int wid  = t >> 5;
    const int lane = t & 31;
    const int wm   = wid >> 2;
    const int wn   = wid & 3;

    const uint32_t sbase = smem_u32(dynsm);

    float c[2][4][4];
    #pragma unroll
    for (int mi = 0; mi < 2; mi++)
        #pragma unroll
        for (int t4 = 0; t4 < 4; t4++)
            #pragma unroll
            for (int r = 0; r < 4; r++) c[mi][t4][r] = 0.f;

    const int la = lane & 15, ga = lane >> 4;
    const int lb = lane & 7,  gb = lane >> 3;

    // ---------- phase 1: q = center @ Wq^T ----------
    {
        auto load_stage = [&](int s, int buf) {
            const int kb = s * 32;
            const uint32_t dstb = sbase + (uint32_t)buf * STGB;
            #pragma unroll
            for (int i = 0; i < 6; i++) {
                int idx = i * 256 + t;
                const __nv_bfloat16* src;
                uint32_t dst;
                if (idx < 512) {
                    int mat = idx >> 8;
                    int rem = idx & 255;
                    int row = rem >> 2, c4 = rem & 3;
                    src = (mat ? g_cl : g_ch) + (size_t)(m0 + row) * EMB + kb + c4 * 8;
                    dst = dstb + (uint32_t)mat * MATB_A + (uint32_t)(row * PADB + c4 * 16);
                } else {
                    int j = idx - 512;
                    int mat = j >> 9;
                    int rem = j & 511;
                    int row = rem >> 2, c4 = rem & 3;
                    src = (mat ? g_wql : g_wqh) + (size_t)row * EMB + kb + c4 * 8;
                    dst = dstb + 2 * MATB_A + (uint32_t)mat * MATB_B
                              + (uint32_t)(row * PADB + c4 * 16);
                }
                CP16(dst, src);
            }
            CPCOMMIT();
        };

        load_stage(0, 0);
        const int nStages = 8;
        for (int s = 0; s < nStages; s++) {
            const int buf = s & 1;
            const bool more = (s + 1 < nStages);
            if (more) load_stage(s + 1, buf ^ 1);
            if (more) CPWAIT1(); else CPWAIT0();
            __syncthreads();

            const uint32_t bS = sbase + (uint32_t)buf * STGB;
            const uint32_t bAhi = bS, bAlo = bS + MATB_A;
            const uint32_t bBhi = bS + 2 * MATB_A, bBlo = bS + 2 * MATB_A + MATB_B;

            #pragma unroll
            for (int kk = 0; kk < 2; kk++) {
                const uint32_t kby = kk * 32;
                uint32_t ah[2][4], al[2][4];
                #pragma unroll
                for (int mi = 0; mi < 2; mi++) {
                    uint32_t adr = (uint32_t)((wm * 32 + mi * 16 + la) * PADB + ga * 16) + kby;
                    LDSM4(ah[mi][0], ah[mi][1], ah[mi][2], ah[mi][3], bAhi + adr);
                    LDSM4(al[mi][0], al[mi][1], al[mi][2], al[mi][3], bAlo + adr);
                }
                uint32_t bh[2][4], bl[2][4];
                #pragma unroll
                for (int nj = 0; nj < 2; nj++) {
                    uint32_t adr = (uint32_t)((wn * 32 + nj * 16 + lb + (gb >> 1) * 8) * PADB
                                              + (gb & 1) * 16) + kby;
                    LDSM4(bh[nj][0], bh[nj][1], bh[nj][2], bh[nj][3], bBhi + adr);
                    LDSM4(bl[nj][0], bl[nj][1], bl[nj][2], bl[nj][3], bBlo + adr);
                }
                #pragma unroll
                for (int mi = 0; mi < 2; mi++)
                    #pragma unroll
                    for (int t4 = 0; t4 < 4; t4++) {
                        const int nj = t4 >> 1, sel = (t4 & 1) * 2;
                        MMA16816(c[mi][t4], ah[mi], bh[nj][sel], bh[nj][sel + 1]);
                        MMA16816(c[mi][t4], al[mi], bh[nj][sel], bh[nj][sel + 1]);
                        MMA16816(c[mi][t4], ah[mi], bl[nj][sel], bl[nj][sel + 1]);
                    }
            }
            __syncthreads();
        }
    }

    // ---------- split q accums into smem ----------
    const int rit  = lane >> 2;
    const int colp = (lane & 3) * 2;
    #pragma unroll
    for (int mi = 0; mi < 2; mi++) {
        #pragma unroll
        for (int half = 0; half < 2; half++) {
            const int row = wm * 32 + mi * 16 + half * 8 + rit;
            #pragma unroll
            for (int t4 = 0; t4 < 4; t4++) {
                const int col = wn * 32 + t4 * 8 + colp;
                float v0 = c[mi][t4][half * 2 + 0];
                float v1 = c[mi][t4][half * 2 + 1];
                __nv_bfloat16 h0 = __float2bfloat16(v0);
                __nv_bfloat16 h1 = __float2bfloat16(v1);
                __nv_bfloat16 l0 = __float2bfloat16(v0 - __bfloat162float(h0));
                __nv_bfloat16 l1 = __float2bfloat16(v1 - __bfloat162float(h1));
                const uint32_t off = (uint32_t)(row * QSTRIDE + col * 2);
                *reinterpret_cast<__nv_bfloat162*>(dynsm + SQ_HI + off) = __nv_bfloat162(h0, h1);
                *reinterpret_cast<__nv_bfloat162*>(dynsm + SQ_LO + off) = __nv_bfloat162(l0, l1);
            }
        }
    }
    __syncthreads();

    // ---------- phase 2: qk ----------
    const uint32_t sqhi = sbase + SQ_HI;
    const uint32_t sqlo = sbase + SQ_LO;
    const uint32_t sbhi = sbase + SB_OFF;
    const uint32_t sblo = sbase + SB_OFF + SB_MATB;

    for (int nt = 0; nt < 4; nt++) {
        const int h   = nt >> 1;
        const int sub = nt & 1;
        const size_t brow0 = (size_t)(h * EMB + sub * 128) * ADIM;

        #pragma unroll
        for (int i = 0; i < 8; i++) {
            int idx = i * 256 + t;
            int mat = idx >> 10;
            int rem = idx & 1023;
            int row = rem >> 3, c8 = rem & 7;
            const __nv_bfloat16* src = (mat ? g_wkl : g_wkh) + brow0 + (size_t)row * ADIM + c8 * 8;
            uint32_t dst = (mat ? sblo : sbhi) + (uint32_t)(row * SB_STR + c8 * 16);
            CP16(dst, src);
        }
        CPCOMMIT(); CPWAIT0();
        __syncthreads();

        #pragma unroll
        for (int mi = 0; mi < 2; mi++)
            #pragma unroll
            for (int t4 = 0; t4 < 4; t4++)
                #pragma unroll
                for (int r = 0; r < 4; r++) c[mi][t4][r] = 0.f;

        #pragma unroll
        for (int kk = 0; kk < 4; kk++) {
            const uint32_t kby = kk * 32;
            uint32_t ah[2][4], al[2][4];
            #pragma unroll
            for (int mi = 0; mi < 2; mi++) {
                uint32_t adr = (uint32_t)((wm * 32 + mi * 16 + la) * QSTRIDE + ga * 16 + h * 128) + kby;
                LDSM4(ah[mi][0], ah[mi][1], ah[mi][2], ah[mi][3], sqhi + adr);
                LDSM4(al[mi][0], al[mi][1], al[mi][2], al[mi][3], sqlo + adr);
            }
            uint32_t bh[2][4], bl[2][4];
            #pragma unroll
            for (int nj = 0; nj < 2; nj++) {
                uint32_t adr = (uint32_t)((wn * 32 + nj * 16 + lb + (gb >> 1) * 8) * SB_STR
                                          + (gb & 1) * 16) + kby;
                LDSM4(bh[nj][0], bh[nj][1], bh[nj][2], bh[nj][3], sbhi + adr);
                LDSM4(bl[nj][0], bl[nj][1], bl[nj][2], bl[nj][3], sblo + adr);
            }
            #pragma unroll
            for (int mi = 0; mi < 2; mi++)
                #pragma unroll
                for (int t4 = 0; t4 < 4; t4++) {
                    const int nj = t4 >> 1, sel = (t4 & 1) * 2;
                    MMA16816(c[mi][t4], ah[mi], bh[nj][sel], bh[nj][sel + 1]);
                    MMA16816(c[mi][t4], al[mi], bh[nj][sel], bh[nj][sel + 1]);
                    MMA16816(c[mi][t4], ah[mi], bl[nj][sel], bl[nj][sel + 1]);
                }
        }

        #pragma unroll
        for (int mi = 0; mi < 2; mi++) {
            #pragma unroll
            for (int half = 0; half < 2; half++) {
                const int gm = m0 + wm * 32 + mi * 16 + half * 8 + rit;
                #pragma unroll
                for (int t4 = 0; t4 < 4; t4++) {
                    const int col = nt * 128 + wn * 32 + t4 * 8 + colp;
                    *reinterpret_cast<float2*>(g_qk + (size_t)gm * 512 + col) =
                        make_float2(c[mi][t4][half * 2 + 0], c[mi][t4][half * 2 + 1]);
                }
            }
        }
        __syncthreads();
    }
}

// ---------------- fused attention (valid) + passthrough copy (invalid) ----------------
// neigh tile loaded via cp.async (L1 bypass), padded row stride 68 float4.
#define SN_STR 68
__global__ __launch_bounds__(128) void attn_kernel(
    const float* __restrict__ center,
    const float* __restrict__ neigh,
    const float* __restrict__ wts,
    const float* __restrict__ qk,
    float* __restrict__ out)
{
    const int i = blockIdx.x;
    const int t = threadIdx.x;
    const int b = g_perm[i];

    if (i >= g_nvalid) {
        const float4* src = reinterpret_cast<const float4*>(center + (long)b * EMB);
        float4*       dst = reinterpret_cast<float4*>(out + (long)b * EMB);
        if (t < 64) dst[t] = src[t];
        return;
    }

    __shared__ float4 sn4[KNEI * SN_STR];   // padded neighbor tile
    __shared__ float4 sq4[128];             // qk both heads
    __shared__ float  sscore[32];
    __shared__ float  sattn[32];

    // cp.async neigh tile: flat float4 f = r*128 + t -> row j = f>>6, col dq = f&63
    const uint32_t snb = smem_u32(sn4);
    const float4* np4 = reinterpret_cast<const float4*>(neigh + (size_t)b * KNEI * EMB);
    #pragma unroll
    for (int r = 0; r < 8; r++) {
        const int f = r * 128 + t;
        const uint32_t dst = snb + (uint32_t)(((f >> 6) * SN_STR + (f & 63)) * 16);
        CP16(dst, np4 + f);
    }
    CPCOMMIT();
    // overlap: qk load through L1 while the bulk tile streams
    sq4[t] = reinterpret_cast<const float4*>(qk + (size_t)i * 512)[t];
    CPWAIT0();
    __syncthreads();

    // scores: group = neighbor j (16 groups x 8 threads), both heads per n-load.
    {
        const int j   = t >> 3;          // 0..15
        const int sub = t & 7;           // 0..7
        const float4* nj4 = sn4 + j * SN_STR;
        float s0 = 0.f, s1 = 0.f;
        #pragma unroll
        for (int ii = 0; ii < 8; ii++) {
            const int d4 = sub + ii * 8;
            const float4 nf = nj4[d4];
            const float4 q0 = sq4[d4];
            const float4 q1 = sq4[64 + d4];
            s0 += nf.x * q0.x + nf.y * q0.y + nf.z * q0.z + nf.w * q0.w;
            s1 += nf.x * q1.x + nf.y * q1.y + nf.z * q1.z + nf.w * q1.w;
        }
        #pragma unroll
        for (int o = 1; o < 8; o <<= 1) {
            s0 += __shfl_xor_sync(0xffffffffu, s0, o);
            s1 += __shfl_xor_sync(0xffffffffu, s1, o);
        }
        if (sub == 0) {
            sscore[j]      = s0 * 0.125f;   // 1/sqrt(64)
            sscore[16 + j] = s1 * 0.125f;
        }
    }
    __syncthreads();

    // softmax * weights, renormalize
    {
        const int wid = t >> 5, lane = t & 31;
        if (wid < NHEADS && lane < KNEI) {
            float s = sscore[wid * KNEI + lane];
            float m = s;
            #pragma unroll
            for (int o = 8; o > 0; o >>= 1) m = fmaxf(m, __shfl_xor_sync(0xffffu, m, o));
            float e = expf(s - m);
            float se = e;
            #pragma unroll
            for (int o = 8; o > 0; o >>= 1) se += __shfl_xor_sync(0xffffu, se, o);
            float a = (e / se) * wts[b * KNEI + lane];
            float sa = a;
            #pragma unroll
            for (int o = 8; o > 0; o >>= 1) sa += __shfl_xor_sync(0xffffu, sa, o);
            sattn[wid * KNEI + lane] = a / (sa + 1e-8f);
        }
    }
    __syncthreads();

    // ctx: thread t -> (h = t>>6, dq = t&63); conflict-free consecutive-dq reads
    {
        const int h  = t >> 6;
        const int dq = t & 63;
        float4 acc = make_float4(0.f, 0.f, 0.f, 0.f);
        #pragma unroll
        for (int jj = 0; jj < KNEI; jj++) {
            const float a = sattn[h * KNEI + jj];
            const float4 nv = sn4[jj * SN_STR + dq];
            acc.x += a * nv.x; acc.y += a * nv.y;
            acc.z += a * nv.z; acc.w += a * nv.w;
        }
        __nv_bfloat16 h0 = __float2bfloat16(acc.x);
        __nv_bfloat16 h1 = __float2bfloat16(acc.y);
        __nv_bfloat16 h2 = __float2bfloat16(acc.z);
        __nv_bfloat16 h3 = __float2bfloat16(acc.w);
        __nv_bfloat16 l0 = __float2bfloat16(acc.x - __bfloat162float(h0));
        __nv_bfloat16 l1 = __float2bfloat16(acc.y - __bfloat162float(h1));
        __nv_bfloat16 l2 = __float2bfloat16(acc.z - __bfloat162float(h2));
        __nv_bfloat16 l3 = __float2bfloat16(acc.w - __bfloat162float(h3));
        const size_t base = (size_t)i * 512 + t * 4;
        *reinterpret_cast<__nv_bfloat162*>(g_cxh + base)     = __nv_bfloat162(h0, h1);
        *reinterpret_cast<__nv_bfloat162*>(g_cxh + base + 2) = __nv_bfloat162(h2, h3);
        *reinterpret_cast<__nv_bfloat162*>(g_cxl + base)     = __nv_bfloat162(l0, l1);
        *reinterpret_cast<__nv_bfloat162*>(g_cxl + base + 2) = __nv_bfloat162(l2, l3);
    }
}

// ---------------- out-GEMM: bf16x3 HMMA, BM=128, BN=128, BK=32, dbl-buffered ----------------
__global__ __launch_bounds__(256, 2) void gemm_mma(
    const __nv_bfloat16* __restrict__ Ahi, const __nv_bfloat16* __restrict__ Alo,
    int lda,
    const __nv_bfloat16* __restrict__ Bhi, const __nv_bfloat16* __restrict__ Blo,
    int ldb, int Kdim,
    float* __restrict__ Cf, int ldcf,
    const float* __restrict__ bias,
    const int* __restrict__ Cperm)
{
    extern __shared__ __align__(16) char dynsm[];

    const int nvalid = g_nvalid;
    const int m0 = blockIdx.y * 128;
    if (m0 >= nvalid) return;
    const int n0 = blockIdx.x * 128;

    const int t    = threadIdx.x;
    const int wid  = t >> 5;
    const int lane = t & 31;
    const int wm   = wid >> 1;
    const int wn   = wid & 1;

    const uint32_t sbase = smem_u32(dynsm);

    float c[2][8][4];
    #pragma unroll
    for (int mi = 0; mi < 2; mi++)
        #pragma unroll
        for (int nj = 0; nj < 8; nj++)
            #pragma unroll
            for (int r = 0; r < 4; r++) c[mi][nj][r] = 0.f;

    const int la = lane & 15, ga = lane >> 4;
    const int lb = lane & 7,  gb = lane >> 3;
    const uint32_t aoff = (uint32_t)((wm * 32 + la) * PADB + ga * 16);
    const uint32_t boff = (uint32_t)((wn * 64 + lb + (gb >> 1) * 8) * PADB + (gb & 1) * 16);

    const int nStages = Kdim >> 5;

    auto load_stage = [&](int s, int buf) {
        const int kb = s * 32;
        const uint32_t dstb = sbase + (uint32_t)buf * OG_STGB;
        #pragma unroll
        for (int i = 0; i < 8; i++) {
            int idx = i * 256 + t;
            int mat = idx >> 9;
            int rem = idx & 511;
            int row = rem >> 2, c4 = rem & 3;
            const __nv_bfloat16* src;
            if (mat == 0)      src = Ahi + (size_t)(m0 + row) * lda + kb + c4 * 8;
            else if (mat == 1) src = Alo + (size_t)(m0 + row) * lda + kb + c4 * 8;
            else if (mat == 2) src = Bhi + (size_t)(n0 + row) * ldb + kb + c4 * 8;
            else               src = Blo + (size_t)(n0 + row) * ldb + kb + c4 * 8;
            uint32_t dst = dstb + (uint32_t)mat * OG_MATB + (uint32_t)(row * PADB + c4 * 16);
            CP16(dst, src);
        }
        CPCOMMIT();
    };

    load_stage(0, 0);

    for (int s = 0; s < nStages; s++) {
        const int buf = s & 1;
        const bool more = (s + 1 < nStages);
        if (more) load_stage(s + 1, buf ^ 1);
        if (more) CPWAIT1(); else CPWAIT0();
        __syncthreads();

        const uint32_t bA = sbase + (uint32_t)buf * OG_STGB;
        const uint32_t bAhi = bA, bAlo = bA + OG_MATB;
        const uint32_t bBhi = bA + 2 * OG_MATB, bBlo = bA + 3 * OG_MATB;

        #pragma unroll
        for (int kk = 0; kk < 2; kk++) {
            const uint32_t kby = kk * 32;
            uint32_t ah[2][4], al[2][4];
            #pragma unroll
            for (int mi = 0; mi < 2; mi++) {
                uint32_t adr = aoff + (uint32_t)(mi * 16 * PADB) + kby;
                LDSM4(ah[mi][0], ah[mi][1], ah[mi][2], ah[mi][3], bAhi + adr);
                LDSM4(al[mi][0], al[mi][1], al[mi][2], al[mi][3], bAlo + adr);
            }
            uint32_t bh[4][4], bl[4][4];
            #pragma unroll
            for (int nj = 0; nj < 4; nj++) {
                uint32_t adr = boff + (uint32_t)(nj * 16 * PADB) + kby;
                LDSM4(bh[nj][0], bh[nj][1], bh[nj][2], bh[nj][3], bBhi + adr);
                LDSM4(bl[nj][0], bl[nj][1], bl[nj][2], bl[nj][3], bBlo + adr);
            }
            #pragma unroll
            for (int mi = 0; mi < 2; mi++)
                #pragma unroll
                for (int t8 = 0; t8 < 8; t8++) {
                    const int nj = t8 >> 1, sel = (t8 & 1) * 2;
                    MMA16816(c[mi][t8], ah[mi], bh[nj][sel], bh[nj][sel + 1]);
                    MMA16816(c[mi][t8], al[mi], bh[nj][sel], bh[nj][sel + 1]);
                    MMA16816(c[mi][t8], ah[mi], bl[nj][sel], bl[nj][sel + 1]);
                }
        }
        __syncthreads();
    }

    const int rit  = lane >> 2;
    const int colp = (lane & 3) * 2;
    #pragma unroll
    for (int mi = 0; mi < 2; mi++) {
        #pragma unroll
        for (int half = 0; half < 2; half++) {
            const int gm = m0 + wm * 32 + mi * 16 + half * 8 + rit;
            if (gm >= nvalid) continue;
            const int crow = Cperm ? Cperm[gm] : gm;
            #pragma unroll
            for (int t8 = 0; t8 < 8; t8++) {
                const int col = n0 + wn * 64 + t8 * 8 + colp;
                float v0 = c[mi][t8][half * 2 + 0];
                float v1 = c[mi][t8][half * 2 + 1];
                if (bias) { v0 += bias[col]; v1 += bias[col + 1]; }
                *reinterpret_cast<float2*>(Cf + (size_t)crow * ldcf + col) =
                    make_float2(v0, v1);
            }
        }
    }
}

// ---------------- launch ----------------
extern "C" void kernel_launch(void* const* d_in, const int* in_sizes, int n_in,
                              void* d_out, int out_size)
{
    const float* center = (const float*)d_in[0];
    const float* neigh  = (const float*)d_in[1];
    const float* wts    = (const float*)d_in[2];
    const void*  mask   = d_in[3];
    const float* Wq     = (const float*)d_in[4];
    const float* Wk     = (const float*)d_in[5];
    const float* Wout   = (const float*)d_in[6];
    const float* bout   = (const float*)d_in[7];
    float* out = (float*)d_out;

    __nv_bfloat16 *cxh, *cxl, *woh, *wol;
    float *gqk;
    int *gperm;
    cudaGetSymbolAddress((void**)&cxh, g_cxh); cudaGetSymbolAddress((void**)&cxl, g_cxl);
    cudaGetSymbolAddress((void**)&woh, g_woh); cudaGetSymbolAddress((void**)&wol, g_wol);
    cudaGetSymbolAddress((void**)&gqk, g_qk);
    cudaGetSymbolAddress((void**)&gperm, g_perm);

    cudaFuncSetAttribute(gemm_mma, cudaFuncAttributeMaxDynamicSharedMemorySize, OG_SMEM);
    cudaFuncSetAttribute(q_qk_fused, cudaFuncAttributeMaxDynamicSharedMemorySize, FUSED_SMEM);

    mask_compact<<<1, 1024>>>(mask);
    prep_gather<<<(PREP_TOT + 255) / 256, 256>>>(Wq, Wk, Wout, center);

    q_qk_fused<<<BATCH / 64, 256, FUSED_SMEM>>>();

    attn_kernel<<<BATCH, 128>>>(center, neigh, wts, gqk, out);

    {
        dim3 grid(2, BATCH / 128);
        gemm_mma<<<grid, 256, OG_SMEM>>>(cxh, cxl, 512, woh, wol, 512, 512,
                                         out, EMB, bout, gperm);
    }
}

// round 16
// speedup vs baseline: 1.3604x; 1.3604x over previous
#include <cuda_runtime.h>
#include <cuda_bf16.h>
#include <math.h>
#include <stdint.h>

#define BATCH  32768
#define EMB    256
#define ADIM   64
#define NHEADS 2
#define KNEI   16

// ---------------- scratch (device globals; no allocation allowed) ----------------
__device__ __nv_bfloat16 g_ch [BATCH * EMB];     // center gathered, bf16 hi
__device__ __nv_bfloat16 g_cl [BATCH * EMB];     // center gathered, bf16 lo
__device__ float         g_qk [BATCH * 512];     // qk fp32 (compacted)
__device__ __nv_bfloat16 g_cxh[BATCH * 512];     // ctx hi
__device__ __nv_bfloat16 g_cxl[BATCH * 512];     // ctx lo
__device__ __nv_bfloat16 g_wqh[128 * 256], g_wql[128 * 256];
__device__ __nv_bfloat16 g_wkh[NHEADS * 256 * 64], g_wkl[NHEADS * 256 * 64];  // WkT [h][d][a]
__device__ __nv_bfloat16 g_woh[256 * 512], g_wol[256 * 512];
__device__ int g_valid[BATCH];
__device__ int g_perm [BATCH];    // [0,nv): valid rows, [nv,BATCH): invalid rows
__device__ int g_nvalid;

// ---------------- helpers ----------------
__device__ __forceinline__ uint32_t smem_u32(const void* p) {
    uint32_t a;
    asm("{ .reg .u64 t; cvta.to.shared.u64 t, %1; cvt.u32.u64 %0, t; }" : "=r"(a) : "l"(p));
    return a;
}

#define LDSM4(r0, r1, r2, r3, addr) \
    asm volatile("ldmatrix.sync.aligned.m8n8.x4.shared.b16 {%0,%1,%2,%3}, [%4];" \
                 : "=r"(r0), "=r"(r1), "=r"(r2), "=r"(r3) : "r"(addr))

#define MMA16816(d, a, b0, b1) \
    asm volatile("mma.sync.aligned.m16n8k16.row.col.f32.bf16.bf16.f32 " \
                 "{%0,%1,%2,%3}, {%4,%5,%6,%7}, {%8,%9}, {%0,%1,%2,%3};" \
                 : "+f"((d)[0]), "+f"((d)[1]), "+f"((d)[2]), "+f"((d)[3]) \
                 : "r"((a)[0]), "r"((a)[1]), "r"((a)[2]), "r"((a)[3]), \
                   "r"(b0), "r"(b1))

#define CP16(dst, src) \
    asm volatile("cp.async.cg.shared.global [%0], [%1], 16;" :: "r"(dst), "l"(src) : "memory")
#define CPCOMMIT() asm volatile("cp.async.commit_group;" ::: "memory")
#define CPWAIT1()  asm volatile("cp.async.wait_group 1;" ::: "memory")
#define CPWAIT0()  asm volatile("cp.async.wait_group 0;" ::: "memory")

__device__ __forceinline__ void split1(float v, __nv_bfloat16* hi, __nv_bfloat16* lo) {
    __nv_bfloat16 h = __float2bfloat16(v);
    *hi = h;
    *lo = __float2bfloat16(v - __bfloat162float(h));
}

// ---------------- mask detect + expand + ordered two-sided compaction ----------------
__global__ void mask_compact(const void* __restrict__ mptr) {
    __shared__ int s[1024];
    __shared__ int flag;
    const int t = threadIdx.x;

    if (t == 0) flag = 0;
    __syncthreads();
    const unsigned int* mw = (const unsigned int*)mptr;
    int found = 0;
    for (int i = t; i < 2048; i += 1024)
        if (mw[i] > 1u) found = 1;
    if (found) flag = 1;
    __syncthreads();
    const int byteMode = flag;

    const int base = t * 32;
    int v[32];
    int c = 0;
    #pragma unroll
    for (int i = 0; i < 32; i++) {
        int b = base + i;
        int val = byteMode ? (((const unsigned char*)mptr)[b] != 0)
                           : (((const int*)mptr)[b] != 0);
        v[i] = val;
        g_valid[b] = val;
        c += val;
    }
    s[t] = c;
    __syncthreads();
    for (int off = 1; off < 1024; off <<= 1) {
        int x = (t >= off) ? s[t - off] : 0;
        __syncthreads();
        s[t] += x;
        __syncthreads();
    }
    const int total = s[1023];
    int o  = s[t] - c;
    int oi = total + (base - o);
    #pragma unroll
    for (int i = 0; i < 32; i++) {
        int b = base + i;
        if (v[i]) g_perm[o++]  = b;
        else      g_perm[oi++] = b;
    }
    if (t == 0) g_nvalid = total;
}

// ---------------- merged prep: weight split/transpose + center gather-split ----------------
#define PREP_W 196608
#define PREP_TOT (PREP_W + BATCH * EMB)

__global__ void prep_gather(const float* __restrict__ Wq,
                            const float* __restrict__ Wk,
                            const float* __restrict__ Wout,
                            const float* __restrict__ center) {
    int idx = blockIdx.x * blockDim.x + threadIdx.x;
    if (idx < 32768) {
        split1(Wq[idx], g_wqh + idx, g_wql + idx);
    } else if (idx < 65536) {
        int j = idx - 32768;
        int h = j / (ADIM * EMB);
        int r = j - h * (ADIM * EMB);
        int a = r / EMB;
        int d = r - a * EMB;
        int o = h * EMB * ADIM + d * ADIM + a;
        split1(Wk[j], g_wkh + o, g_wkl + o);
    } else if (idx < PREP_W) {
        int j = idx - 65536;
        split1(Wout[j], g_woh + j, g_wol + j);
    } else {
        int j = idx - PREP_W;
        int row = j >> 8, d = j & 255;
        if (row < g_nvalid) {
            float v = center[(size_t)g_perm[row] * EMB + d];
            split1(v, g_ch + j, g_cl + j);
        }
    }
}

// ======================= q_qk fused kernel constants (BM=64, BN=128) =======================
#define PADB   80
#define MATB_A (64 * PADB)
#define MATB_B (128 * PADB)
#define STGB   (2 * MATB_A + 2 * MATB_B)   // 30720

#define QSTRIDE 272
#define SQ_HI   0
#define SQ_LO   (64 * QSTRIDE)
#define SB_OFF  (2 * 64 * QSTRIDE)         // 34816
#define SB_STR  144
#define SB_MATB (128 * SB_STR)             // 18432
// phase-2 B tiles double buffered: 2 buffers x (hi+lo)
#define FUSED_SMEM (SB_OFF + 4 * SB_MATB)  // 108544 -> 2 CTAs/SM

// ======================= out-GEMM constants (BM=128, BN=128) =======================
#define OG_MATB (128 * PADB)
#define OG_STGB (4 * OG_MATB)
#define OG_SMEM (2 * OG_STGB)              // 81920

// ---------------- fused q -> qk kernel (BM=64) ----------------
__global__ __launch_bounds__(256, 2) void q_qk_fused()
{
    extern __shared__ __align__(16) char dynsm[];

    const int nvalid = g_nvalid;
    const int m0 = blockIdx.x * 64;
    if (m0 >= nvalid) return;

    const int t    = threadIdx.x;
    const int wid  = t >> 5;
    const int lane = t & 31;
    const int wm   = wid >> 2;
    const int wn   = wid & 3;

    const uint32_t sbase = smem_u32(dynsm);

    float c[2][4][4];
    #pragma unroll
    for (int mi = 0; mi < 2; mi++)
        #pragma unroll
        for (int t4 = 0; t4 < 4; t4++)
            #pragma unroll
            for (int r = 0; r < 4; r++) c[mi][t4][r] = 0.f;

    const int la = lane & 15, ga = lane >> 4;
    const int lb = lane & 7,  gb = lane >> 3;

    // ---------- phase 1: q = center @ Wq^T ----------
    {
        auto load_stage = [&](int s, int buf) {
            const int kb = s * 32;
            const uint32_t dstb = sbase + (uint32_t)buf * STGB;
            #pragma unroll
            for (int i = 0; i < 6; i++) {
                int idx = i * 256 + t;
                const __nv_bfloat16* src;
                uint32_t dst;
                if (idx < 512) {
                    int mat = idx >> 8;
                    int rem = idx & 255;
                    int row = rem >> 2, c4 = rem & 3;
                    src = (mat ? g_cl : g_ch) + (size_t)(m0 + row) * EMB + kb + c4 * 8;
                    dst = dstb + (uint32_t)mat * MATB_A + (uint32_t)(row * PADB + c4 * 16);
                } else {
                    int j = idx - 512;
                    int mat = j >> 9;
                    int rem = j & 511;
                    int row = rem >> 2, c4 = rem & 3;
                    src = (mat ? g_wql : g_wqh) + (size_t)row * EMB + kb + c4 * 8;
                    dst = dstb + 2 * MATB_A + (uint32_t)mat * MATB_B
                              + (uint32_t)(row * PADB + c4 * 16);
                }
                CP16(dst, src);
            }
            CPCOMMIT();
        };

        load_stage(0, 0);
        const int nStages = 8;
        for (int s = 0; s < nStages; s++) {
            const int buf = s & 1;
            const bool more = (s + 1 < nStages);
            if (more) load_stage(s + 1, buf ^ 1);
            if (more) CPWAIT1(); else CPWAIT0();
            __syncthreads();

            const uint32_t bS = sbase + (uint32_t)buf * STGB;
            const uint32_t bAhi = bS, bAlo = bS + MATB_A;
            const uint32_t bBhi = bS + 2 * MATB_A, bBlo = bS + 2 * MATB_A + MATB_B;

            #pragma unroll
            for (int kk = 0; kk < 2; kk++) {
                const uint32_t kby = kk * 32;
                uint32_t ah[2][4], al[2][4];
                #pragma unroll
                for (int mi = 0; mi < 2; mi++) {
                    uint32_t adr = (uint32_t)((wm * 32 + mi * 16 + la) * PADB + ga * 16) + kby;
                    LDSM4(ah[mi][0], ah[mi][1], ah[mi][2], ah[mi][3], bAhi + adr);
                    LDSM4(al[mi][0], al[mi][1], al[mi][2], al[mi][3], bAlo + adr);
                }
                uint32_t bh[2][4], bl[2][4];
                #pragma unroll
                for (int nj = 0; nj < 2; nj++) {
                    uint32_t adr = (uint32_t)((wn * 32 + nj * 16 + lb + (gb >> 1) * 8) * PADB
                                              + (gb & 1) * 16) + kby;
                    LDSM4(bh[nj][0], bh[nj][1], bh[nj][2], bh[nj][3], bBhi + adr);
                    LDSM4(bl[nj][0], bl[nj][1], bl[nj][2], bl[nj][3], bBlo + adr);
                }
                #pragma unroll
                for (int mi = 0; mi < 2; mi++)
                    #pragma unroll
                    for (int t4 = 0; t4 < 4; t4++) {
                        const int nj = t4 >> 1, sel = (t4 & 1) * 2;
                        MMA16816(c[mi][t4], ah[mi], bh[nj][sel], bh[nj][sel + 1]);
                        MMA16816(c[mi][t4], al[mi], bh[nj][sel], bh[nj][sel + 1]);
                        MMA16816(c[mi][t4], ah[mi], bl[nj][sel], bl[nj][sel + 1]);
                    }
            }
            __syncthreads();
        }
    }

    // ---------- split q accums into smem ----------
    const int rit  = lane >> 2;
    const int colp = (lane & 3) * 2;
    #pragma unroll
    for (int mi = 0; mi < 2; mi++) {
        #pragma unroll
        for (int half = 0; half < 2; half++) {
            const int row = wm * 32 + mi * 16 + half * 8 + rit;
            #pragma unroll
            for (int t4 = 0; t4 < 4; t4++) {
                const int col = wn * 32 + t4 * 8 + colp;
                float v0 = c[mi][t4][half * 2 + 0];
                float v1 = c[mi][t4][half * 2 + 1];
                __nv_bfloat16 h0 = __float2bfloat16(v0);
                __nv_bfloat16 h1 = __float2bfloat16(v1);
                __nv_bfloat16 l0 = __float2bfloat16(v0 - __bfloat162float(h0));
                __nv_bfloat16 l1 = __float2bfloat16(v1 - __bfloat162float(h1));
                const uint32_t off = (uint32_t)(row * QSTRIDE + col * 2);
                *reinterpret_cast<__nv_bfloat162*>(dynsm + SQ_HI + off) = __nv_bfloat162(h0, h1);
                *reinterpret_cast<__nv_bfloat162*>(dynsm + SQ_LO + off) = __nv_bfloat162(l0, l1);
            }
        }
    }
    __syncthreads();

    // ---------- phase 2: qk, WkT tiles double buffered ----------
    const uint32_t sqhi = sbase + SQ_HI;
    const uint32_t sqlo = sbase + SQ_LO;

    auto load_wk = [&](int nt, int buf) {
        const int h   = nt >> 1;
        const int sub = nt & 1;
        const size_t brow0 = (size_t)(h * EMB + sub * 128) * ADIM;
        const uint32_t base = sbase + SB_OFF + (uint32_t)buf * (2 * SB_MATB);
        #pragma unroll
        for (int i = 0; i < 8; i++) {
            int idx = i * 256 + t;
            int mat = idx >> 10;
            int rem = idx & 1023;
            int row = rem >> 3, c8 = rem & 7;
            const __nv_bfloat16* src = (mat ? g_wkl : g_wkh) + brow0 + (size_t)row * ADIM + c8 * 8;
            uint32_t dst = base + (uint32_t)mat * SB_MATB + (uint32_t)(row * SB_STR + c8 * 16);
            CP16(dst, src);
        }
        CPCOMMIT();
    };

    load_wk(0, 0);

    for (int nt = 0; nt < 4; nt++) {
        const int buf = nt & 1;
        const bool more = (nt + 1 < 4);
        if (more) load_wk(nt + 1, buf ^ 1);
        if (more) CPWAIT1(); else CPWAIT0();
        __syncthreads();

        const int h = nt >> 1;
        const uint32_t sbhi = sbase + SB_OFF + (uint32_t)buf * (2 * SB_MATB);
        const uint32_t sblo = sbhi + SB_MATB;

        #pragma unroll
        for (int mi = 0; mi < 2; mi++)
            #pragma unroll
            for (int t4 = 0; t4 < 4; t4++)
                #pragma unroll
                for (int r = 0; r < 4; r++) c[mi][t4][r] = 0.f;

        #pragma unroll
        for (int kk = 0; kk < 4; kk++) {
            const uint32_t kby = kk * 32;
            uint32_t ah[2][4], al[2][4];
            #pragma unroll
            for (int mi = 0; mi < 2; mi++) {
                uint32_t adr = (uint32_t)((wm * 32 + mi * 16 + la) * QSTRIDE + ga * 16 + h * 128) + kby;
                LDSM4(ah[mi][0], ah[mi][1], ah[mi][2], ah[mi][3], sqhi + adr);
                LDSM4(al[mi][0], al[mi][1], al[mi][2], al[mi][3], sqlo + adr);
            }
            uint32_t bh[2][4], bl[2][4];
            #pragma unroll
            for (int nj = 0; nj < 2; nj++) {
                uint32_t adr = (uint32_t)((wn * 32 + nj * 16 + lb + (gb >> 1) * 8) * SB_STR
                                          + (gb & 1) * 16) + kby;
                LDSM4(bh[nj][0], bh[nj][1], bh[nj][2], bh[nj][3], sbhi + adr);
                LDSM4(bl[nj][0], bl[nj][1], bl[nj][2], bl[nj][3], sblo + adr);
            }
            #pragma unroll
            for (int mi = 0; mi < 2; mi++)
                #pragma unroll
                for (int t4 = 0; t4 < 4; t4++) {
                    const int nj = t4 >> 1, sel = (t4 & 1) * 2;
                    MMA16816(c[mi][t4], ah[mi], bh[nj][sel], bh[nj][sel + 1]);
                    MMA16816(c[mi][t4], al[mi], bh[nj][sel], bh[nj][sel + 1]);
                    MMA16816(c[mi][t4], ah[mi], bl[nj][sel], bl[nj][sel + 1]);
                }
        }

        #pragma unroll
        for (int mi = 0; mi < 2; mi++) {
            #pragma unroll
            for (int half = 0; half < 2; half++) {
                const int gm = m0 + wm * 32 + mi * 16 + half * 8 + rit;
                #pragma unroll
                for (int t4 = 0; t4 < 4; t4++) {
                    const int col = nt * 128 + wn * 32 + t4 * 8 + colp;
                    *reinterpret_cast<float2*>(g_qk + (size_t)gm * 512 + col) =
                        make_float2(c[mi][t4][half * 2 + 0], c[mi][t4][half * 2 + 1]);
                }
            }
        }
        __syncthreads();
    }
}

// ---------------- fused attention (R14 proven version) ----------------
#define SN_STR 68
__global__ __launch_bounds__(128) void attn_kernel(
    const float* __restrict__ center,
    const float* __restrict__ neigh,
    const float* __restrict__ wts,
    const float* __restrict__ qk,
    float* __restrict__ out)
{
    const int i = blockIdx.x;
    const int t = threadIdx.x;
    const int b = g_perm[i];

    if (i >= g_nvalid) {
        const float4* src = reinterpret_cast<const float4*>(center + (long)b * EMB);
        float4*       dst = reinterpret_cast<float4*>(out + (long)b * EMB);
        if (t < 64) dst[t] = src[t];
        return;
    }

    __shared__ float4 sn4[KNEI * SN_STR];   // padded neighbor tile
    __shared__ float4 sq4[128];             // qk both heads
    __shared__ float  sscore[32];
    __shared__ float  sattn[32];

    // coalesced load: flat float4 f = r*128 + t -> row j = f>>6, col dq = f&63
    const float4* np4 = reinterpret_cast<const float4*>(neigh + (size_t)b * KNEI * EMB);
    #pragma unroll
    for (int r = 0; r < 8; r++) {
        const int f = r * 128 + t;
        sn4[(f >> 6) * SN_STR + (f & 63)] = np4[f];
    }
    sq4[t] = reinterpret_cast<const float4*>(qk + (size_t)i * 512)[t];
    __syncthreads();

    // scores: group = neighbor j (16 groups x 8 threads), both heads per n-load.
    {
        const int j   = t >> 3;          // 0..15
        const int sub = t & 7;           // 0..7
        const float4* nj4 = sn4 + j * SN_STR;
        float s0 = 0.f, s1 = 0.f;
        #pragma unroll
        for (int ii = 0; ii < 8; ii++) {
            const int d4 = sub + ii * 8;
            const float4 nf = nj4[d4];
            const float4 q0 = sq4[d4];
            const float4 q1 = sq4[64 + d4];
            s0 += nf.x * q0.x + nf.y * q0.y + nf.z * q0.z + nf.w * q0.w;
            s1 += nf.x * q1.x + nf.y * q1.y + nf.z * q1.z + nf.w * q1.w;
        }
        #pragma unroll
        for (int o = 1; o < 8; o <<= 1) {
            s0 += __shfl_xor_sync(0xffffffffu, s0, o);
            s1 += __shfl_xor_sync(0xffffffffu, s1, o);
        }
        if (sub == 0) {
            sscore[j]      = s0 * 0.125f;   // 1/sqrt(64)
            sscore[16 + j] = s1 * 0.125f;
        }
    }
    __syncthreads();

    // softmax * weights, renormalize
    {
        const int wid = t >> 5, lane = t & 31;
        if (wid < NHEADS && lane < KNEI) {
            float s = sscore[wid * KNEI + lane];
            float m = s;
            #pragma unroll
            for (int o = 8; o > 0; o >>= 1) m = fmaxf(m, __shfl_xor_sync(0xffffu, m, o));
            float e = expf(s - m);
            float se = e;
            #pragma unroll
            for (int o = 8; o > 0; o >>= 1) se += __shfl_xor_sync(0xffffu, se, o);
            float a = (e / se) * wts[b * KNEI + lane];
            float sa = a;
            #pragma unroll
            for (int o = 8; o > 0; o >>= 1) sa += __shfl_xor_sync(0xffffu, sa, o);
            sattn[wid * KNEI + lane] = a / (sa + 1e-8f);
        }
    }
    __syncthreads();

    // ctx: thread t -> (h = t>>6, dq = t&63); conflict-free consecutive-dq reads
    {
        const int h  = t >> 6;
        const int dq = t & 63;
        float4 acc = make_float4(0.f, 0.f, 0.f, 0.f);
        #pragma unroll
        for (int jj = 0; jj < KNEI; jj++) {
            const float a = sattn[h * KNEI + jj];
            const float4 nv = sn4[jj * SN_STR + dq];
            acc.x += a * nv.x; acc.y += a * nv.y;
            acc.z += a * nv.z; acc.w += a * nv.w;
        }
        __nv_bfloat16 h0 = __float2bfloat16(acc.x);
        __nv_bfloat16 h1 = __float2bfloat16(acc.y);
        __nv_bfloat16 h2 = __float2bfloat16(acc.z);
        __nv_bfloat16 h3 = __float2bfloat16(acc.w);
        __nv_bfloat16 l0 = __float2bfloat16(acc.x - __bfloat162float(h0));
        __nv_bfloat16 l1 = __float2bfloat16(acc.y - __bfloat162float(h1));
        __nv_bfloat16 l2 = __float2bfloat16(acc.z - __bfloat162float(h2));
        __nv_bfloat16 l3 = __float2bfloat16(acc.w - __bfloat162float(h3));
        const size_t base = (size_t)i * 512 + t * 4;
        *reinterpret_cast<__nv_bfloat162*>(g_cxh + base)     = __nv_bfloat162(h0, h1);
        *reinterpret_cast<__nv_bfloat162*>(g_cxh + base + 2) = __nv_bfloat162(h2, h3);
        *reinterpret_cast<__nv_bfloat162*>(g_cxl + base)     = __nv_bfloat162(l0, l1);
        *reinterpret_cast<__nv_bfloat162*>(g_cxl + base + 2) = __nv_bfloat162(l2, l3);
    }
}

// ---------------- out-GEMM: bf16x3 HMMA, BM=128, BN=128, BK=32, dbl-buffered ----------------
__global__ __launch_bounds__(256, 2) void gemm_mma(
    const __nv_bfloat16* __restrict__ Ahi, const __nv_bfloat16* __restrict__ Alo,
    int lda,
    const __nv_bfloat16* __restrict__ Bhi, const __nv_bfloat16* __restrict__ Blo,
    int ldb, int Kdim,
    float* __restrict__ Cf, int ldcf,
    const float* __restrict__ bias,
    const int* __restrict__ Cperm)
{
    extern __shared__ __align__(16) char dynsm[];

    const int nvalid = g_nvalid;
    const int m0 = blockIdx.y * 128;
    if (m0 >= nvalid) return;
    const int n0 = blockIdx.x * 128;

    const int t    = threadIdx.x;
    const int wid  = t >> 5;
    const int lane = t & 31;
    const int wm   = wid >> 1;
    const int wn   = wid & 1;

    const uint32_t sbase = smem_u32(dynsm);

    float c[2][8][4];
    #pragma unroll
    for (int mi = 0; mi < 2; mi++)
        #pragma unroll
        for (int nj = 0; nj < 8; nj++)
            #pragma unroll
            for (int r = 0; r < 4; r++) c[mi][nj][r] = 0.f;

    const int la = lane & 15, ga = lane >> 4;
    const int lb = lane & 7,  gb = lane >> 3;
    const uint32_t aoff = (uint32_t)((wm * 32 + la) * PADB + ga * 16);
    const uint32_t boff = (uint32_t)((wn * 64 + lb + (gb >> 1) * 8) * PADB + (gb & 1) * 16);

    const int nStages = Kdim >> 5;

    auto load_stage = [&](int s, int buf) {
        const int kb = s * 32;
        const uint32_t dstb = sbase + (uint32_t)buf * OG_STGB;
        #pragma unroll
        for (int i = 0; i < 8; i++) {
            int idx = i * 256 + t;
            int mat = idx >> 9;
            int rem = idx & 511;
            int row = rem >> 2, c4 = rem & 3;
            const __nv_bfloat16* src;
            if (mat == 0)      src = Ahi + (size_t)(m0 + row) * lda + kb + c4 * 8;
            else if (mat == 1) src = Alo + (size_t)(m0 + row) * lda + kb + c4 * 8;
            else if (mat == 2) src = Bhi + (size_t)(n0 + row) * ldb + kb + c4 * 8;
            else               src = Blo + (size_t)(n0 + row) * ldb + kb + c4 * 8;
            uint32_t dst = dstb + (uint32_t)mat * OG_MATB + (uint32_t)(row * PADB + c4 * 16);
            CP16(dst, src);
        }
        CPCOMMIT();
    };

    load_stage(0, 0);

    for (int s = 0; s < nStages; s++) {
        const int buf = s & 1;
        const bool more = (s + 1 < nStages);
        if (more) load_stage(s + 1, buf ^ 1);
        if (more) CPWAIT1(); else CPWAIT0();
        __syncthreads();

        const uint32_t bA = sbase + (uint32_t)buf * OG_STGB;
        const uint32_t bAhi = bA, bAlo = bA + OG_MATB;
        const uint32_t bBhi = bA + 2 * OG_MATB, bBlo = bA + 3 * OG_MATB;

        #pragma unroll
        for (int kk = 0; kk < 2; kk++) {
            const uint32_t kby = kk * 32;
            uint32_t ah[2][4], al[2][4];
            #pragma unroll
            for (int mi = 0; mi < 2; mi++) {
                uint32_t adr = aoff + (uint32_t)(mi * 16 * PADB) + kby;
                LDSM4(ah[mi][0], ah[mi][1], ah[mi][2], ah[mi][3], bAhi + adr);
                LDSM4(al[mi][0], al[mi][1], al[mi][2], al[mi][3], bAlo + adr);
            }
            uint32_t bh[4][4], bl[4][4];
            #pragma unroll
            for (int nj = 0; nj < 4; nj++) {
                uint32_t adr = boff + (uint32_t)(nj * 16 * PADB) + kby;
                LDSM4(bh[nj][0], bh[nj][1], bh[nj][2], bh[nj][3], bBhi + adr);
                LDSM4(bl[nj][0], bl[nj][1], bl[nj][2], bl[nj][3], bBlo + adr);
            }
            #pragma unroll
            for (int mi = 0; mi < 2; mi++)
                #pragma unroll
                for (int t8 = 0; t8 < 8; t8++) {
                    const int nj = t8 >> 1, sel = (t8 & 1) * 2;
                    MMA16816(c[mi][t8], ah[mi], bh[nj][sel], bh[nj][sel + 1]);
                    MMA16816(c[mi][t8], al[mi], bh[nj][sel], bh[nj][sel + 1]);
                    MMA16816(c[mi][t8], ah[mi], bl[nj][sel], bl[nj][sel + 1]);
                }
        }
        __syncthreads();
    }

    const int rit  = lane >> 2;
    const int colp = (lane & 3) * 2;
    #pragma unroll
    for (int mi = 0; mi < 2; mi++) {
        #pragma unroll
        for (int half = 0; half < 2; half++) {
            const int gm = m0 + wm * 32 + mi * 16 + half * 8 + rit;
            if (gm >= nvalid) continue;
            const int crow = Cperm ? Cperm[gm] : gm;
            #pragma unroll
            for (int t8 = 0; t8 < 8; t8++) {
                const int col = n0 + wn * 64 + t8 * 8 + colp;
                float v0 = c[mi][t8][half * 2 + 0];
                float v1 = c[mi][t8][half * 2 + 1];
                if (bias) { v0 += bias[col]; v1 += bias[col + 1]; }
                *reinterpret_cast<float2*>(Cf + (size_t)crow * ldcf + col) =
                    make_float2(v0, v1);
            }
        }
    }
}

// ---------------- launch ----------------
extern "C" void kernel_launch(void* const* d_in, const int* in_sizes, int n_in,
                              void* d_out, int out_size)
{
    const float* center = (const float*)d_in[0];
    const float* neigh  = (const float*)d_in[1];
    const float* wts    = (const float*)d_in[2];
    const void*  mask   = d_in[3];
    const float* Wq     = (const float*)d_in[4];
    const float* Wk     = (const float*)d_in[5];
    const float* Wout   = (const float*)d_in[6];
    const float* bout   = (const float*)d_in[7];
    float* out = (float*)d_out;

    __nv_bfloat16 *cxh, *cxl, *woh, *wol;
    float *gqk;
    int *gperm;
    cudaGetSymbolAddress((void**)&cxh, g_cxh); cudaGetSymbolAddress((void**)&cxl, g_cxl);
    cudaGetSymbolAddress((void**)&woh, g_woh); cudaGetSymbolAddress((void**)&wol, g_wol);
    cudaGetSymbolAddress((void**)&gqk, g_qk);
    cudaGetSymbolAddress((void**)&gperm, g_perm);

    cudaFuncSetAttribute(gemm_mma, cudaFuncAttributeMaxDynamicSharedMemorySize, OG_SMEM);
    cudaFuncSetAttribute(q_qk_fused, cudaFuncAttributeMaxDynamicSharedMemorySize, FUSED_SMEM);

    mask_compact<<<1, 1024>>>(mask);
    prep_gather<<<(PREP_TOT + 255) / 256, 256>>>(Wq, Wk, Wout, center);

    q_qk_fused<<<BATCH / 64, 256, FUSED_SMEM>>>();

    attn_kernel<<<BATCH, 128>>>(center, neigh, wts, gqk, out);

    {
        dim3 grid(2, BATCH / 128);
        gemm_mma<<<grid, 256, OG_SMEM>>>(cxh, cxl, 512, woh, wol, 512, 512,
                                         out, EMB, bout, gperm);
    }
}

// round 17
// speedup vs baseline: 1.3636x; 1.0023x over previous
#include <cuda_runtime.h>
#include <cuda_bf16.h>
#include <math.h>
#include <stdint.h>

#define BATCH  32768
#define EMB    256
#define ADIM   64
#define NHEADS 2
#define KNEI   16

// ---------------- scratch (device globals; no allocation allowed) ----------------
__device__ __nv_bfloat16 g_ch [BATCH * EMB];     // center gathered, bf16 hi
__device__ __nv_bfloat16 g_cl [BATCH * EMB];     // center gathered, bf16 lo
__device__ float         g_qk [BATCH * 512];     // qk fp32 (compacted)
__device__ __nv_bfloat16 g_cxh[BATCH * 512];     // ctx hi
__device__ __nv_bfloat16 g_cxl[BATCH * 512];     // ctx lo
__device__ __nv_bfloat16 g_wqh[128 * 256], g_wql[128 * 256];
__device__ __nv_bfloat16 g_wkh[NHEADS * 256 * 64], g_wkl[NHEADS * 256 * 64];  // WkT [h][d][a]
__device__ __nv_bfloat16 g_woh[256 * 512], g_wol[256 * 512];
__device__ int g_valid[BATCH];
__device__ int g_perm [BATCH];    // [0,nv): valid rows, [nv,BATCH): invalid rows
__device__ int g_nvalid;

// ---------------- helpers ----------------
__device__ __forceinline__ uint32_t smem_u32(const void* p) {
    uint32_t a;
    asm("{ .reg .u64 t; cvta.to.shared.u64 t, %1; cvt.u32.u64 %0, t; }" : "=r"(a) : "l"(p));
    return a;
}

#define LDSM4(r0, r1, r2, r3, addr) \
    asm volatile("ldmatrix.sync.aligned.m8n8.x4.shared.b16 {%0,%1,%2,%3}, [%4];" \
                 : "=r"(r0), "=r"(r1), "=r"(r2), "=r"(r3) : "r"(addr))

#define MMA16816(d, a, b0, b1) \
    asm volatile("mma.sync.aligned.m16n8k16.row.col.f32.bf16.bf16.f32 " \
                 "{%0,%1,%2,%3}, {%4,%5,%6,%7}, {%8,%9}, {%0,%1,%2,%3};" \
                 : "+f"((d)[0]), "+f"((d)[1]), "+f"((d)[2]), "+f"((d)[3]) \
                 : "r"((a)[0]), "r"((a)[1]), "r"((a)[2]), "r"((a)[3]), \
                   "r"(b0), "r"(b1))

#define CP16(dst, src) \
    asm volatile("cp.async.cg.shared.global [%0], [%1], 16;" :: "r"(dst), "l"(src) : "memory")
#define CPCOMMIT() asm volatile("cp.async.commit_group;" ::: "memory")
#define CPWAIT1()  asm volatile("cp.async.wait_group 1;" ::: "memory")
#define CPWAIT0()  asm volatile("cp.async.wait_group 0;" ::: "memory")

__device__ __forceinline__ void split1(float v, __nv_bfloat16* hi, __nv_bfloat16* lo) {
    __nv_bfloat16 h = __float2bfloat16(v);
    *hi = h;
    *lo = __float2bfloat16(v - __bfloat162float(h));
}

// ---------------- mask detect + expand + ordered two-sided compaction ----------------
__global__ void mask_compact(const void* __restrict__ mptr) {
    __shared__ int s[1024];
    __shared__ int flag;
    const int t = threadIdx.x;

    if (t == 0) flag = 0;
    __syncthreads();
    const unsigned int* mw = (const unsigned int*)mptr;
    int found = 0;
    for (int i = t; i < 2048; i += 1024)
        if (mw[i] > 1u) found = 1;
    if (found) flag = 1;
    __syncthreads();
    const int byteMode = flag;

    const int base = t * 32;
    int v[32];
    int c = 0;
    #pragma unroll
    for (int i = 0; i < 32; i++) {
        int b = base + i;
        int val = byteMode ? (((const unsigned char*)mptr)[b] != 0)
                           : (((const int*)mptr)[b] != 0);
        v[i] = val;
        g_valid[b] = val;
        c += val;
    }
    s[t] = c;
    __syncthreads();
    for (int off = 1; off < 1024; off <<= 1) {
        int x = (t >= off) ? s[t - off] : 0;
        __syncthreads();
        s[t] += x;
        __syncthreads();
    }
    const int total = s[1023];
    int o  = s[t] - c;
    int oi = total + (base - o);
    #pragma unroll
    for (int i = 0; i < 32; i++) {
        int b = base + i;
        if (v[i]) g_perm[o++]  = b;
        else      g_perm[oi++] = b;
    }
    if (t == 0) g_nvalid = total;
}

// ---------------- merged prep: weights + center gather + invalid passthrough ----------------
// ranges: [0, 196608) weight split/transpose
//         [196608, 196608 + B*256) center gather-split for compacted valid rows
//         [.., + B*64) invalid-row passthrough out = center (float4 granularity)
#define PREP_W   196608
#define PREP_G   (PREP_W + BATCH * EMB)
#define PREP_TOT (PREP_G + BATCH * 64)

__global__ void prep_gather(const float* __restrict__ Wq,
                            const float* __restrict__ Wk,
                            const float* __restrict__ Wout,
                            const float* __restrict__ center,
                            float* __restrict__ out) {
    int idx = blockIdx.x * blockDim.x + threadIdx.x;
    if (idx < 32768) {
        split1(Wq[idx], g_wqh + idx, g_wql + idx);
    } else if (idx < 65536) {
        int j = idx - 32768;
        int h = j / (ADIM * EMB);
        int r = j - h * (ADIM * EMB);
        int a = r / EMB;
        int d = r - a * EMB;
        int o = h * EMB * ADIM + d * ADIM + a;
        split1(Wk[j], g_wkh + o, g_wkl + o);
    } else if (idx < PREP_W) {
        int j = idx - 65536;
        split1(Wout[j], g_woh + j, g_wol + j);
    } else if (idx < PREP_G) {
        int j = idx - PREP_W;
        int row = j >> 8, d = j & 255;
        if (row < g_nvalid) {
            float v = center[(size_t)g_perm[row] * EMB + d];
            split1(v, g_ch + j, g_cl + j);
        }
    } else {
        int j = idx - PREP_G;          // float4 index over BATCH*64
        int b = j >> 6;
        if (!g_valid[b])
            reinterpret_cast<float4*>(out)[j] =
                reinterpret_cast<const float4*>(center)[j];
    }
}

// ======================= q_qk fused kernel constants (BM=64, BN=128) =======================
#define PADB   80
#define MATB_A (64 * PADB)
#define MATB_B (128 * PADB)
#define STGB   (2 * MATB_A + 2 * MATB_B)   // 30720

#define QSTRIDE 272
#define SQ_HI   0
#define SQ_LO   (64 * QSTRIDE)
#define SB_OFF  (2 * 64 * QSTRIDE)         // 34816
#define SB_STR  144
#define SB_MATB (128 * SB_STR)             // 18432
#define FUSED_SMEM (SB_OFF + 4 * SB_MATB)  // 108544 -> 2 CTAs/SM

// ======================= out-GEMM constants (BM=128, BN=128) =======================
#define OG_MATB (128 * PADB)
#define OG_STGB (4 * OG_MATB)
#define OG_SMEM (2 * OG_STGB)              // 81920

// ---------------- fused q -> qk kernel (BM=64) ----------------
__global__ __launch_bounds__(256, 2) void q_qk_fused()
{
    extern __shared__ __align__(16) char dynsm[];

    const int nvalid = g_nvalid;
    const int m0 = blockIdx.x * 64;
    if (m0 >= nvalid) return;

    const int t    = threadIdx.x;
    const int wid  = t >> 5;
    const int lane = t & 31;
    const int wm   = wid >> 2;
    const int wn   = wid & 3;

    const uint32_t sbase = smem_u32(dynsm);

    float c[2][4][4];
    #pragma unroll
    for (int mi = 0; mi < 2; mi++)
        #pragma unroll
        for (int t4 = 0; t4 < 4; t4++)
            #pragma unroll
            for (int r = 0; r < 4; r++) c[mi][t4][r] = 0.f;

    const int la = lane & 15, ga = lane >> 4;
    const int lb = lane & 7,  gb = lane >> 3;

    // ---------- phase 1: q = center @ Wq^T ----------
    {
        auto load_stage = [&](int s, int buf) {
            const int kb = s * 32;
            const uint32_t dstb = sbase + (uint32_t)buf * STGB;
            #pragma unroll
            for (int i = 0; i < 6; i++) {
                int idx = i * 256 + t;
                const __nv_bfloat16* src;
                uint32_t dst;
                if (idx < 512) {
                    int mat = idx >> 8;
                    int rem = idx & 255;
                    int row = rem >> 2, c4 = rem & 3;
                    src = (mat ? g_cl : g_ch) + (size_t)(m0 + row) * EMB + kb + c4 * 8;
                    dst = dstb + (uint32_t)mat * MATB_A + (uint32_t)(row * PADB + c4 * 16);
                } else {
                    int j = idx - 512;
                    int mat = j >> 9;
                    int rem = j & 511;
                    int row = rem >> 2, c4 = rem & 3;
                    src = (mat ? g_wql : g_wqh) + (size_t)row * EMB + kb + c4 * 8;
                    dst = dstb + 2 * MATB_A + (uint32_t)mat * MATB_B
                              + (uint32_t)(row * PADB + c4 * 16);
                }
                CP16(dst, src);
            }
            CPCOMMIT();
        };

        load_stage(0, 0);
        const int nStages = 8;
        for (int s = 0; s < nStages; s++) {
            const int buf = s & 1;
            const bool more = (s + 1 < nStages);
            if (more) load_stage(s + 1, buf ^ 1);
            if (more) CPWAIT1(); else CPWAIT0();
            __syncthreads();

            const uint32_t bS = sbase + (uint32_t)buf * STGB;
            const uint32_t bAhi = bS, bAlo = bS + MATB_A;
            const uint32_t bBhi = bS + 2 * MATB_A, bBlo = bS + 2 * MATB_A + MATB_B;

            #pragma unroll
            for (int kk = 0; kk < 2; kk++) {
                const uint32_t kby = kk * 32;
                uint32_t ah[2][4], al[2][4];
                #pragma unroll
                for (int mi = 0; mi < 2; mi++) {
                    uint32_t adr = (uint32_t)((wm * 32 + mi * 16 + la) * PADB + ga * 16) + kby;
                    LDSM4(ah[mi][0], ah[mi][1], ah[mi][2], ah[mi][3], bAhi + adr);
                    LDSM4(al[mi][0], al[mi][1], al[mi][2], al[mi][3], bAlo + adr);
                }
                uint32_t bh[2][4], bl[2][4];
                #pragma unroll
                for (int nj = 0; nj < 2; nj++) {
                    uint32_t adr = (uint32_t)((wn * 32 + nj * 16 + lb + (gb >> 1) * 8) * PADB
                                              + (gb & 1) * 16) + kby;
                    LDSM4(bh[nj][0], bh[nj][1], bh[nj][2], bh[nj][3], bBhi + adr);
                    LDSM4(bl[nj][0], bl[nj][1], bl[nj][2], bl[nj][3], bBlo + adr);
                }
                #pragma unroll
                for (int mi = 0; mi < 2; mi++)
                    #pragma unroll
                    for (int t4 = 0; t4 < 4; t4++) {
                        const int nj = t4 >> 1, sel = (t4 & 1) * 2;
                        MMA16816(c[mi][t4], ah[mi], bh[nj][sel], bh[nj][sel + 1]);
                        MMA16816(c[mi][t4], al[mi], bh[nj][sel], bh[nj][sel + 1]);
                        MMA16816(c[mi][t4], ah[mi], bl[nj][sel], bl[nj][sel + 1]);
                    }
            }
            __syncthreads();
        }
    }

    // ---------- split q accums into smem ----------
    const int rit  = lane >> 2;
    const int colp = (lane & 3) * 2;
    #pragma unroll
    for (int mi = 0; mi < 2; mi++) {
        #pragma unroll
        for (int half = 0; half < 2; half++) {
            const int row = wm * 32 + mi * 16 + half * 8 + rit;
            #pragma unroll
            for (int t4 = 0; t4 < 4; t4++) {
                const int col = wn * 32 + t4 * 8 + colp;
                float v0 = c[mi][t4][half * 2 + 0];
                float v1 = c[mi][t4][half * 2 + 1];
                __nv_bfloat16 h0 = __float2bfloat16(v0);
                __nv_bfloat16 h1 = __float2bfloat16(v1);
                __nv_bfloat16 l0 = __float2bfloat16(v0 - __bfloat162float(h0));
                __nv_bfloat16 l1 = __float2bfloat16(v1 - __bfloat162float(h1));
                const uint32_t off = (uint32_t)(row * QSTRIDE + col * 2);
                *reinterpret_cast<__nv_bfloat162*>(dynsm + SQ_HI + off) = __nv_bfloat162(h0, h1);
                *reinterpret_cast<__nv_bfloat162*>(dynsm + SQ_LO + off) = __nv_bfloat162(l0, l1);
            }
        }
    }
    __syncthreads();

    // ---------- phase 2: qk, WkT tiles double buffered ----------
    const uint32_t sqhi = sbase + SQ_HI;
    const uint32_t sqlo = sbase + SQ_LO;

    auto load_wk = [&](int nt, int buf) {
        const int h   = nt >> 1;
        const int sub = nt & 1;
        const size_t brow0 = (size_t)(h * EMB + sub * 128) * ADIM;
        const uint32_t base = sbase + SB_OFF + (uint32_t)buf * (2 * SB_MATB);
        #pragma unroll
        for (int i = 0; i < 8; i++) {
            int idx = i * 256 + t;
            int mat = idx >> 10;
            int rem = idx & 1023;
            int row = rem >> 3, c8 = rem & 7;
            const __nv_bfloat16* src = (mat ? g_wkl : g_wkh) + brow0 + (size_t)row * ADIM + c8 * 8;
            uint32_t dst = base + (uint32_t)mat * SB_MATB + (uint32_t)(row * SB_STR + c8 * 16);
            CP16(dst, src);
        }
        CPCOMMIT();
    };

    load_wk(0, 0);

    for (int nt = 0; nt < 4; nt++) {
        const int buf = nt & 1;
        const bool more = (nt + 1 < 4);
        if (more) load_wk(nt + 1, buf ^ 1);
        if (more) CPWAIT1(); else CPWAIT0();
        __syncthreads();

        const int h = nt >> 1;
        const uint32_t sbhi = sbase + SB_OFF + (uint32_t)buf * (2 * SB_MATB);
        const uint32_t sblo = sbhi + SB_MATB;

        #pragma unroll
        for (int mi = 0; mi < 2; mi++)
            #pragma unroll
            for (int t4 = 0; t4 < 4; t4++)
                #pragma unroll
                for (int r = 0; r < 4; r++) c[mi][t4][r] = 0.f;

        #pragma unroll
        for (int kk = 0; kk < 4; kk++) {
            const uint32_t kby = kk * 32;
            uint32_t ah[2][4], al[2][4];
            #pragma unroll
            for (int mi = 0; mi < 2; mi++) {
                uint32_t adr = (uint32_t)((wm * 32 + mi * 16 + la) * QSTRIDE + ga * 16 + h * 128) + kby;
                LDSM4(ah[mi][0], ah[mi][1], ah[mi][2], ah[mi][3], sqhi + adr);
                LDSM4(al[mi][0], al[mi][1], al[mi][2], al[mi][3], sqlo + adr);
            }
            uint32_t bh[2][4], bl[2][4];
            #pragma unroll
            for (int nj = 0; nj < 2; nj++) {
                uint32_t adr = (uint32_t)((wn * 32 + nj * 16 + lb + (gb >> 1) * 8) * SB_STR
                                          + (gb & 1) * 16) + kby;
                LDSM4(bh[nj][0], bh[nj][1], bh[nj][2], bh[nj][3], sbhi + adr);
                LDSM4(bl[nj][0], bl[nj][1], bl[nj][2], bl[nj][3], sblo + adr);
            }
            #pragma unroll
            for (int mi = 0; mi < 2; mi++)
                #pragma unroll
                for (int t4 = 0; t4 < 4; t4++) {
                    const int nj = t4 >> 1, sel = (t4 & 1) * 2;
                    MMA16816(c[mi][t4], ah[mi], bh[nj][sel], bh[nj][sel + 1]);
                    MMA16816(c[mi][t4], al[mi], bh[nj][sel], bh[nj][sel + 1]);
                    MMA16816(c[mi][t4], ah[mi], bl[nj][sel], bl[nj][sel + 1]);
                }
        }

        #pragma unroll
        for (int mi = 0; mi < 2; mi++) {
            #pragma unroll
            for (int half = 0; half < 2; half++) {
                const int gm = m0 + wm * 32 + mi * 16 + half * 8 + rit;
                #pragma unroll
                for (int t4 = 0; t4 < 4; t4++) {
                    const int col = nt * 128 + wn * 32 + t4 * 8 + colp;
                    *reinterpret_cast<float2*>(g_qk + (size_t)gm * 512 + col) =
                        make_float2(c[mi][t4][half * 2 + 0], c[mi][t4][half * 2 + 1]);
                }
            }
        }
        __syncthreads();
    }
}

// ---------------- fused attention: 2 rows per CTA (256 threads) ----------------
// warps 0-3 = row 2*blockIdx.x, warps 4-7 = row 2*blockIdx.x+1, independent halves.
// Invalid halves idle through barriers (passthrough handled by prep_gather).
#define SN_STR 68
__global__ __launch_bounds__(256) void attn_kernel(
    const float* __restrict__ neigh,
    const float* __restrict__ wts,
    const float* __restrict__ qk)
{
    __shared__ float4 sn4[2][KNEI * SN_STR];
    __shared__ float4 sq4[2][128];
    __shared__ float  sscore[2][32];
    __shared__ float  sattn[2][32];

    const int half = threadIdx.x >> 7;      // 0 or 1
    const int t    = threadIdx.x & 127;
    const int i    = blockIdx.x * 2 + half;
    const bool v   = (i < g_nvalid);
    const int b    = g_perm[i];

    if (v) {
        const float4* np4 = reinterpret_cast<const float4*>(neigh + (size_t)b * KNEI * EMB);
        #pragma unroll
        for (int r = 0; r < 8; r++) {
            const int f = r * 128 + t;
            sn4[half][(f >> 6) * SN_STR + (f & 63)] = np4[f];
        }
        sq4[half][t] = reinterpret_cast<const float4*>(qk + (size_t)i * 512)[t];
    }
    __syncthreads();

    // scores
    if (v) {
        const int j   = t >> 3;
        const int sub = t & 7;
        const float4* nj4 = sn4[half] + j * SN_STR;
        float s0 = 0.f, s1 = 0.f;
        #pragma unroll
        for (int ii = 0; ii < 8; ii++) {
            const int d4 = sub + ii * 8;
            const float4 nf = nj4[d4];
            const float4 q0 = sq4[half][d4];
            const float4 q1 = sq4[half][64 + d4];
            s0 += nf.x * q0.x + nf.y * q0.y + nf.z * q0.z + nf.w * q0.w;
            s1 += nf.x * q1.x + nf.y * q1.y + nf.z * q1.z + nf.w * q1.w;
        }
        #pragma unroll
        for (int o = 1; o < 8; o <<= 1) {
            s0 += __shfl_xor_sync(0xffffffffu, s0, o);
            s1 += __shfl_xor_sync(0xffffffffu, s1, o);
        }
        if (sub == 0) {
            sscore[half][j]      = s0 * 0.125f;
            sscore[half][16 + j] = s1 * 0.125f;
        }
    }
    __syncthreads();

    // softmax * weights, renormalize (warps 0,1 of each half -> heads 0,1)
    if (v) {
        const int wid = t >> 5, lane = t & 31;
        if (wid < NHEADS && lane < KNEI) {
            float s = sscore[half][wid * KNEI + lane];
            float m = s;
            #pragma unroll
            for (int o = 8; o > 0; o >>= 1) m = fmaxf(m, __shfl_xor_sync(0xffffu, m, o));
            float e = expf(s - m);
            float se = e;
            #pragma unroll
            for (int o = 8; o > 0; o >>= 1) se += __shfl_xor_sync(0xffffu, se, o);
            float a = (e / se) * wts[b * KNEI + lane];
            float sa = a;
            #pragma unroll
            for (int o = 8; o > 0; o >>= 1) sa += __shfl_xor_sync(0xffffu, sa, o);
            sattn[half][wid * KNEI + lane] = a / (sa + 1e-8f);
        }
    }
    __syncthreads();

    // ctx
    if (v) {
        const int h  = t >> 6;
        const int dq = t & 63;
        float4 acc = make_float4(0.f, 0.f, 0.f, 0.f);
        #pragma unroll
        for (int jj = 0; jj < KNEI; jj++) {
            const float a = sattn[half][h * KNEI + jj];
            const float4 nv = sn4[half][jj * SN_STR + dq];
            acc.x += a * nv.x; acc.y += a * nv.y;
            acc.z += a * nv.z; acc.w += a * nv.w;
        }
        __nv_bfloat16 h0 = __float2bfloat16(acc.x);
        __nv_bfloat16 h1 = __float2bfloat16(acc.y);
        __nv_bfloat16 h2 = __float2bfloat16(acc.z);
        __nv_bfloat16 h3 = __float2bfloat16(acc.w);
        __nv_bfloat16 l0 = __float2bfloat16(acc.x - __bfloat162float(h0));
        __nv_bfloat16 l1 = __float2bfloat16(acc.y - __bfloat162float(h1));
        __nv_bfloat16 l2 = __float2bfloat16(acc.z - __bfloat162float(h2));
        __nv_bfloat16 l3 = __float2bfloat16(acc.w - __bfloat162float(h3));
        const size_t base = (size_t)i * 512 + t * 4;
        *reinterpret_cast<__nv_bfloat162*>(g_cxh + base)     = __nv_bfloat162(h0, h1);
        *reinterpret_cast<__nv_bfloat162*>(g_cxh + base + 2) = __nv_bfloat162(h2, h3);
        *reinterpret_cast<__nv_bfloat162*>(g_cxl + base)     = __nv_bfloat162(l0, l1);
        *reinterpret_cast<__nv_bfloat162*>(g_cxl + base + 2) = __nv_bfloat162(l2, l3);
    }
}

// ---------------- out-GEMM: bf16x3 HMMA, BM=128, BN=128, BK=32, dbl-buffered ----------------
__global__ __launch_bounds__(256, 2) void gemm_mma(
    const __nv_bfloat16* __restrict__ Ahi, const __nv_bfloat16* __restrict__ Alo,
    int lda,
    const __nv_bfloat16* __restrict__ Bhi, const __nv_bfloat16* __restrict__ Blo,
    int ldb, int Kdim,
    float* __restrict__ Cf, int ldcf,
    const float* __restrict__ bias,
    const int* __restrict__ Cperm)
{
    extern __shared__ __align__(16) char dynsm[];

    const int nvalid = g_nvalid;
    const int m0 = blockIdx.y * 128;
    if (m0 >= nvalid) return;
    const int n0 = blockIdx.x * 128;

    const int t    = threadIdx.x;
    const int wid  = t >> 5;
    const int lane = t & 31;
    const int wm   = wid >> 1;
    const int wn   = wid & 1;

    const uint32_t sbase = smem_u32(dynsm);

    float c[2][8][4];
    #pragma unroll
    for (int mi = 0; mi < 2; mi++)
        #pragma unroll
        for (int nj = 0; nj < 8; nj++)
            #pragma unroll
            for (int r = 0; r < 4; r++) c[mi][nj][r] = 0.f;

    const int la = lane & 15, ga = lane >> 4;
    const int lb = lane & 7,  gb = lane >> 3;
    const uint32_t aoff = (uint32_t)((wm * 32 + la) * PADB + ga * 16);
    const uint32_t boff = (uint32_t)((wn * 64 + lb + (gb >> 1) * 8) * PADB + (gb & 1) * 16);

    const int nStages = Kdim >> 5;

    auto load_stage = [&](int s, int buf) {
        const int kb = s * 32;
        const uint32_t dstb = sbase + (uint32_t)buf * OG_STGB;
        #pragma unroll
        for (int i = 0; i < 8; i++) {
            int idx = i * 256 + t;
            int mat = idx >> 9;
            int rem = idx & 511;
            int row = rem >> 2, c4 = rem & 3;
            const __nv_bfloat16* src;
            if (mat == 0)      src = Ahi + (size_t)(m0 + row) * lda + kb + c4 * 8;
            else if (mat == 1) src = Alo + (size_t)(m0 + row) * lda + kb + c4 * 8;
            else if (mat == 2) src = Bhi + (size_t)(n0 + row) * ldb + kb + c4 * 8;
            else               src = Blo + (size_t)(n0 + row) * ldb + kb + c4 * 8;
            uint32_t dst = dstb + (uint32_t)mat * OG_MATB + (uint32_t)(row * PADB + c4 * 16);
            CP16(dst, src);
        }
        CPCOMMIT();
    };

    load_stage(0, 0);

    for (int s = 0; s < nStages; s++) {
        const int buf = s & 1;
        const bool more = (s + 1 < nStages);
        if (more) load_stage(s + 1, buf ^ 1);
        if (more) CPWAIT1(); else CPWAIT0();
        __syncthreads();

        const uint32_t bA = sbase + (uint32_t)buf * OG_STGB;
        const uint32_t bAhi = bA, bAlo = bA + OG_MATB;
        const uint32_t bBhi = bA + 2 * OG_MATB, bBlo = bA + 3 * OG_MATB;

        #pragma unroll
        for (int kk = 0; kk < 2; kk++) {
            const uint32_t kby = kk * 32;
            uint32_t ah[2][4], al[2][4];
            #pragma unroll
            for (int mi = 0; mi < 2; mi++) {
                uint32_t adr = aoff + (uint32_t)(mi * 16 * PADB) + kby;
                LDSM4(ah[mi][0], ah[mi][1], ah[mi][2], ah[mi][3], bAhi + adr);
                LDSM4(al[mi][0], al[mi][1], al[mi][2], al[mi][3], bAlo + adr);
            }
            uint32_t bh[4][4], bl[4][4];
            #pragma unroll
            for (int nj = 0; nj < 4; nj++) {
                uint32_t adr = boff + (uint32_t)(nj * 16 * PADB) + kby;
                LDSM4(bh[nj][0], bh[nj][1], bh[nj][2], bh[nj][3], bBhi + adr);
                LDSM4(bl[nj][0], bl[nj][1], bl[nj][2], bl[nj][3], bBlo + adr);
            }
            #pragma unroll
            for (int mi = 0; mi < 2; mi++)
                #pragma unroll
                for (int t8 = 0; t8 < 8; t8++) {
                    const int nj = t8 >> 1, sel = (t8 & 1) * 2;
                    MMA16816(c[mi][t8], ah[mi], bh[nj][sel], bh[nj][sel + 1]);
                    MMA16816(c[mi][t8], al[mi], bh[nj][sel], bh[nj][sel + 1]);
                    MMA16816(c[mi][t8], ah[mi], bl[nj][sel], bl[nj][sel + 1]);
                }
        }
        __syncthreads();
    }

    const int rit  = lane >> 2;
    const int colp = (lane & 3) * 2;
    #pragma unroll
    for (int mi = 0; mi < 2; mi++) {
        #pragma unroll
        for (int half = 0; half < 2; half++) {
            const int gm = m0 + wm * 32 + mi * 16 + half * 8 + rit;
            if (gm >= nvalid) continue;
            const int crow = Cperm ? Cperm[gm] : gm;
            #pragma unroll
            for (int t8 = 0; t8 < 8; t8++) {
                const int col = n0 + wn * 64 + t8 * 8 + colp;
                float v0 = c[mi][t8][half * 2 + 0];
                float v1 = c[mi][t8][half * 2 + 1];
                if (bias) { v0 += bias[col]; v1 += bias[col + 1]; }
                *reinterpret_cast<float2*>(Cf + (size_t)crow * ldcf + col) =
                    make_float2(v0, v1);
            }
        }
    }
}

// ---------------- launch ----------------
extern "C" void kernel_launch(void* const* d_in, const int* in_sizes, int n_in,
                              void* d_out, int out_size)
{
    const float* center = (const float*)d_in[0];
    const float* neigh  = (const float*)d_in[1];
    const float* wts    = (const float*)d_in[2];
    const void*  mask   = d_in[3];
    const float* Wq     = (const float*)d_in[4];
    const float* Wk     = (const float*)d_in[5];
    const float* Wout   = (const float*)d_in[6];
    const float* bout   = (const float*)d_in[7];
    float* out = (float*)d_out;

    __nv_bfloat16 *cxh, *cxl, *woh, *wol;
    float *gqk;
    int *gperm;
    cudaGetSymbolAddress((void**)&cxh, g_cxh); cudaGetSymbolAddress((void**)&cxl, g_cxl);
    cudaGetSymbolAddress((void**)&woh, g_woh); cudaGetSymbolAddress((void**)&wol, g_wol);
    cudaGetSymbolAddress((void**)&gqk, g_qk);
    cudaGetSymbolAddress((void**)&gperm, g_perm);

    cudaFuncSetAttribute(gemm_mma, cudaFuncAttributeMaxDynamicSharedMemorySize, OG_SMEM);
    cudaFuncSetAttribute(q_qk_fused, cudaFuncAttributeMaxDynamicSharedMemorySize, FUSED_SMEM);

    mask_compact<<<1, 1024>>>(mask);
    prep_gather<<<(PREP_TOT + 255) / 256, 256>>>(Wq, Wk, Wout, center, out);

    q_qk_fused<<<BATCH / 64, 256, FUSED_SMEM>>>();

    // attention: 2 rows per CTA
    attn_kernel<<<BATCH / 2, 256>>>(neigh, wts, gqk);

    {
        dim3 grid(2, BATCH / 128);
        gemm_mma<<<grid, 256, OG_SMEM>>>(cxh, cxl, 512, woh, wol, 512, 512,
                                         out, EMB, bout, gperm);
    }
}